// round 6
// baseline (speedup 1.0000x reference)
#include <cuda_runtime.h>
#include <cuda_bf16.h>
#include <cstdint>

#define DEV_INLINE __device__ __forceinline__

static constexpr int N_FEAT = 131072;
static constexpr int DIM    = 128;
static constexpr int K_CENT = 1024;

static constexpr int M_TILE   = 256;     // rows per CTA (8 warps x 32 rows)
static constexpr int NC_CHUNK = 128;     // centers per smem chunk
static constexpr int NUM_CHUNKS = K_CENT / NC_CHUNK;   // 8
static constexpr int GRID = N_FEAT / M_TILE;           // 512

static constexpr int ROW = 144;          // 128 fp8 bytes + 16B pad (conflict-free ldmatrix)
static constexpr int SMEM_A_BYTES = M_TILE * ROW;          // 36864
static constexpr int SMEM_B_BYTES = NC_CHUNK * ROW;        // 18432 per buffer
static constexpr int SMEM_TOTAL   = SMEM_A_BYTES + 2 * SMEM_B_BYTES;  // 73728

// ---------------- device scratch (no allocations allowed) ----------------
__device__ uint8_t g_cb[(size_t)K_CENT * DIM];   // normalized centers, e4m3
__device__ double  g_partial[GRID];
__device__ unsigned int g_ticket;                // zero-init; finisher resets each run

// ---------------- helpers ----------------
DEV_INLINE uint32_t smem_u32(const void* p) {
    uint32_t a;
    asm("{ .reg .u64 t; cvta.to.shared.u64 t, %1; cvt.u32.u64 %0, t; }" : "=r"(a) : "l"(p));
    return a;
}

DEV_INLINE void ldmatrix_x4(uint32_t* r, uint32_t addr) {
    asm volatile("ldmatrix.sync.aligned.m8n8.x4.shared.b16 {%0,%1,%2,%3}, [%4];"
                 : "=r"(r[0]), "=r"(r[1]), "=r"(r[2]), "=r"(r[3]) : "r"(addr));
}

// fp8 e4m3 MMA: m16n8k32, f32 accumulate (sm_89+ base PTX; no tcgen05 needed)
DEV_INLINE void mma_fp8(float* c, const uint32_t* a, uint32_t b0, uint32_t b1) {
    asm volatile(
        "mma.sync.aligned.m16n8k32.row.col.f32.e4m3.e4m3.f32 "
        "{%0,%1,%2,%3}, {%4,%5,%6,%7}, {%8,%9}, {%0,%1,%2,%3};"
        : "+f"(c[0]), "+f"(c[1]), "+f"(c[2]), "+f"(c[3])
        : "r"(a[0]), "r"(a[1]), "r"(a[2]), "r"(a[3]), "r"(b0), "r"(b1));
}

// pack 4 floats -> 4 e4m3 bytes (x at lowest address)
DEV_INLINE uint32_t pack_e4m3x4(float x, float y, float z, float w) {
    uint32_t lo, hi;
    asm("{ .reg .b16 t; cvt.rn.satfinite.e4m3x2.f32 t, %1, %2; cvt.u32.u16 %0, t; }"
        : "=r"(lo) : "f"(y), "f"(x));
    asm("{ .reg .b16 t; cvt.rn.satfinite.e4m3x2.f32 t, %1, %2; cvt.u32.u16 %0, t; }"
        : "=r"(hi) : "f"(w), "f"(z));
    return lo | (hi << 16);
}

DEV_INLINE void cp_async16(uint32_t smem_dst, const void* gmem_src) {
    asm volatile("cp.async.ca.shared.global [%0], [%1], 16;"
                 :: "r"(smem_dst), "l"(gmem_src) : "memory");
}
DEV_INLINE void cp_async_commit() { asm volatile("cp.async.commit_group;" ::: "memory"); }
DEV_INLINE void cp_async_wait_all() { asm volatile("cp.async.wait_group 0;" ::: "memory"); }

// ---------------- prep: normalize centers -> e4m3 ----------------
__global__ void prep_centers_kernel(const float* __restrict__ cent) {
    int warp = (blockIdx.x * blockDim.x + threadIdx.x) >> 5;
    int lid  = threadIdx.x & 31;
    if (warp >= K_CENT) return;
    const float4 v = reinterpret_cast<const float4*>(cent + (size_t)warp * DIM)[lid];
    float s = v.x * v.x + v.y * v.y + v.z * v.z + v.w * v.w;
    #pragma unroll
    for (int o = 16; o; o >>= 1) s += __shfl_xor_sync(0xFFFFFFFFu, s, o);
    float inv = 1.0f / fmaxf(sqrtf(s), 1e-12f);
    reinterpret_cast<uint32_t*>(g_cb + (size_t)warp * DIM)[lid] =
        pack_e4m3x4(v.x * inv, v.y * inv, v.z * inv, v.w * inv);
}

// ---------------- fused: normalize + fp8 GEMM + argmax + loss + finalize ----------------
// Accumulators init to 2.0f so sim+2 in [1,3] (positive float = int-monotone).
// key = (bits & ~0x3FF) | (1023 - idx); integer max == argmax, first-index tie-break.
__global__ void __launch_bounds__(256, 2)
argmax_loss_kernel(const float* __restrict__ feat, const float* __restrict__ cent,
                   float* __restrict__ out) {
    extern __shared__ char smem[];
    char* As = smem;
    const uint32_t a_s = smem_u32(As);
    const uint32_t b_s = a_s + SMEM_A_BYTES;

    __shared__ float  inv_s[M_TILE];
    __shared__ double wsum[8];
    __shared__ int    is_last;

    const int tid  = threadIdx.x;
    const int w    = tid >> 5;
    const int lane = tid & 31;
    const size_t rowbase = (size_t)blockIdx.x * M_TILE;

    // ---- load + L2-normalize 32 rows/warp, convert to e4m3, store to smem A ----
    #pragma unroll 4
    for (int r = 0; r < 32; r++) {
        const int row = w * 32 + r;
        const float4 v = reinterpret_cast<const float4*>(feat + (rowbase + row) * DIM)[lane];
        float s = v.x * v.x + v.y * v.y + v.z * v.z + v.w * v.w;
        #pragma unroll
        for (int o = 16; o; o >>= 1) s += __shfl_xor_sync(0xFFFFFFFFu, s, o);
        float inv = 1.0f / fmaxf(sqrtf(s), 1e-12f);
        if (lane == 0) inv_s[row] = inv;
        *reinterpret_cast<uint32_t*>(As + row * ROW + lane * 4) =
            pack_e4m3x4(v.x * inv, v.y * inv, v.z * inv, v.w * inv);
    }

    // ---- stage B chunk 0 (cp.async) ----
    const uint8_t* cb = g_cb;
    {
        #pragma unroll
        for (int i = 0; i < 4; i++) {
            const int t = tid + i * 256;             // 1024 x 16B = 16KB chunk
            const int row = t >> 3, seg = t & 7;
            cp_async16(b_s + row * ROW + seg * 16, cb + row * 128 + seg * 16);
        }
        cp_async_commit();
    }
    cp_async_wait_all();
    __syncthreads();

    // ---- A fragments in registers: 2 m16-blocks x 4 k32-steps x 4 regs ----
    uint32_t af[2][4][4];
    {
        const int arow = lane & 15;
        const int acol = (lane >> 4) * 16;
        #pragma unroll
        for (int mb = 0; mb < 2; mb++)
            #pragma unroll
            for (int ks = 0; ks < 4; ks++)
                ldmatrix_x4(af[mb][ks], a_s + (w * 32 + mb * 16 + arow) * ROW + acol + ks * 32);
    }

    int key[4];
    #pragma unroll
    for (int i = 0; i < 4; i++) key[i] = (int)0x80000000;

    const uint32_t bfrag_off = (lane & 7) * ROW + (lane >> 3) * 16;

    for (int c = 0; c < NUM_CHUNKS; c++) {
        const uint32_t bufbase = b_s + (c & 1) * SMEM_B_BYTES;

        if (c < NUM_CHUNKS - 1) {   // prefetch next chunk into the other buffer
            const uint8_t* src = cb + (size_t)(c + 1) * NC_CHUNK * 128;
            const uint32_t dst = b_s + ((c + 1) & 1) * SMEM_B_BYTES;
            #pragma unroll
            for (int i = 0; i < 4; i++) {
                const int t = tid + i * 256;
                const int row = t >> 3, seg = t & 7;
                cp_async16(dst + row * ROW + seg * 16, src + row * 128 + seg * 16);
            }
            cp_async_commit();
        }

        const int codeA0 = 1023 - (c * NC_CHUNK + 2 * (lane & 3));

        #pragma unroll
        for (int nt = 0; nt < 16; nt++) {
            float c0[4] = {2.0f, 2.0f, 2.0f, 2.0f};
            float c1[4] = {2.0f, 2.0f, 2.0f, 2.0f};
            uint32_t b[8];
            const uint32_t baddr = bufbase + nt * 8 * ROW + bfrag_off;
            ldmatrix_x4(b,     baddr);        // k bytes 0..63
            ldmatrix_x4(b + 4, baddr + 64);   // k bytes 64..127

            mma_fp8(c0, af[0][0], b[0], b[1]);
            mma_fp8(c1, af[1][0], b[0], b[1]);
            mma_fp8(c0, af[0][1], b[2], b[3]);
            mma_fp8(c1, af[1][1], b[2], b[3]);
            mma_fp8(c0, af[0][2], b[4], b[5]);
            mma_fp8(c1, af[1][2], b[4], b[5]);
            mma_fp8(c0, af[0][3], b[6], b[7]);
            mma_fp8(c1, af[1][3], b[6], b[7]);

            const int cA = codeA0 - nt * 8;
            const int cB = cA - 1;
            key[0] = max(key[0], (int)((__float_as_uint(c0[0]) & 0xFFFFFC00u) | (uint32_t)cA));
            key[0] = max(key[0], (int)((__float_as_uint(c0[1]) & 0xFFFFFC00u) | (uint32_t)cB));
            key[1] = max(key[1], (int)((__float_as_uint(c0[2]) & 0xFFFFFC00u) | (uint32_t)cA));
            key[1] = max(key[1], (int)((__float_as_uint(c0[3]) & 0xFFFFFC00u) | (uint32_t)cB));
            key[2] = max(key[2], (int)((__float_as_uint(c1[0]) & 0xFFFFFC00u) | (uint32_t)cA));
            key[2] = max(key[2], (int)((__float_as_uint(c1[1]) & 0xFFFFFC00u) | (uint32_t)cB));
            key[3] = max(key[3], (int)((__float_as_uint(c1[2]) & 0xFFFFFC00u) | (uint32_t)cA));
            key[3] = max(key[3], (int)((__float_as_uint(c1[3]) & 0xFFFFFC00u) | (uint32_t)cB));
        }

        if (c < NUM_CHUNKS - 1) cp_async_wait_all();
        __syncthreads();   // buffer (c&1) free for reuse; next buffer ready
    }

    // ---- reduce keys across quad (cols live in 4 lanes) ----
    #pragma unroll
    for (int o = 1; o <= 2; o <<= 1)
        #pragma unroll
        for (int i = 0; i < 4; i++)
            key[i] = max(key[i], __shfl_xor_sync(0xFFFFFFFFu, key[i], o));

    // distribute: thread 'lane' owns row w*32+lane; its key lives at lane (lane&7)*4, slot lane>>3
    const int srcl = (lane & 7) * 4;
    const int k0 = __shfl_sync(0xFFFFFFFFu, key[0], srcl);
    const int k1 = __shfl_sync(0xFFFFFFFFu, key[1], srcl);
    const int k2 = __shfl_sync(0xFFFFFFFFu, key[2], srcl);
    const int k3 = __shfl_sync(0xFFFFFFFFu, key[3], srcl);
    const int sel = lane >> 3;
    const int kk = sel == 0 ? k0 : sel == 1 ? k1 : sel == 2 ? k2 : k3;
    const int bi = 1023 - (kk & 1023);     // assignment for row rowbase + w*32 + lane

    // ---- fused loss: exact fp32 terms (features re-read, L2-hot), fp64 warp accumulate ----
    double acc = 0.0;
    for (int r = 0; r < 32; r++) {
        const int a = __shfl_sync(0xFFFFFFFFu, bi, r);
        const int row = w * 32 + r;
        const float4 v  = reinterpret_cast<const float4*>(feat + (rowbase + row) * DIM)[lane];
        const float4 cv = reinterpret_cast<const float4*>(cent + (size_t)a * DIM)[lane];
        const float inv = inv_s[row];
        float dx = v.x * inv - cv.x;
        float dy = v.y * inv - cv.y;
        float dz = v.z * inv - cv.z;
        float dw = v.w * inv - cv.w;
        float t = dx * dx + dy * dy + dz * dz + dw * dw;
        #pragma unroll
        for (int o = 16; o; o >>= 1) t += __shfl_xor_sync(0xFFFFFFFFu, t, o);
        if (lane == 0) acc += (double)t;
    }
    if (lane == 0) wsum[w] = acc;
    __syncthreads();

    if (tid == 0) {
        double s = 0.0;
        #pragma unroll
        for (int i = 0; i < 8; i++) s += wsum[i];
        g_partial[blockIdx.x] = s;
        __threadfence();
        unsigned int t = atomicAdd(&g_ticket, 1u);
        is_last = (t == (unsigned)(GRID - 1));
    }
    __syncthreads();

    // ---- last CTA finalizes (deterministic fixed-order sum); resets ticket for replay ----
    if (is_last) {
        double* sd = reinterpret_cast<double*>(smem);   // A region no longer needed
        volatile double* gp = g_partial;
        double s = gp[tid] + gp[tid + 256];
        sd[tid] = s;
        __syncthreads();
        for (int o = 128; o; o >>= 1) {
            if (tid < o) sd[tid] += sd[tid + o];
            __syncthreads();
        }
        if (tid == 0) {
            out[0] = (float)(sd[0] / (double)N_FEAT);
            g_ticket = 0;
        }
    }
}

// ---------------- launch ----------------
extern "C" void kernel_launch(void* const* d_in, const int* in_sizes, int n_in,
                              void* d_out, int out_size) {
    const float* feat = (const float*)d_in[0];
    const float* cent = (const float*)d_in[1];

    static bool attr_set = false;
    if (!attr_set) {
        cudaFuncSetAttribute(argmax_loss_kernel, cudaFuncAttributeMaxDynamicSharedMemorySize, SMEM_TOTAL);
        attr_set = true;
    }

    prep_centers_kernel<<<K_CENT / 8, 256>>>(cent);
    argmax_loss_kernel<<<GRID, 256, SMEM_TOTAL>>>(feat, cent, (float*)d_out);
}